// round 1
// baseline (speedup 1.0000x reference)
#include <cuda_runtime.h>
#include <cstdint>
#include <math.h>

#define NN 8192   // nodes / A dim / E
#define HD 1024   // hidden dim
#define EE 8192   // edges

// ---- scratch (device globals; allocation-free per harness rules) ----
__device__ float g_H1[(size_t)NN * HD];   // 32 MB
__device__ float g_H2[(size_t)NN * NN];   // 256 MB
__device__ float g_d2[NN];
__device__ float g_acc[3];                // loss1, loss2, lossr

__global__ void zero_acc_kernel() {
    g_acc[0] = 0.f; g_acc[1] = 0.f; g_acc[2] = 0.f;
}

// ---- block reduction (256 threads) ----
__device__ __forceinline__ float block_reduce(float v) {
    __shared__ float sh[8];
    __syncthreads();
    int lane = threadIdx.x & 31;
    int w    = threadIdx.x >> 5;
#pragma unroll
    for (int o = 16; o > 0; o >>= 1) v += __shfl_down_sync(0xffffffffu, v, o);
    if (lane == 0) sh[w] = v;
    __syncthreads();
    if (w == 0) {
        v = (lane < 8) ? sh[lane] : 0.f;
#pragma unroll
        for (int o = 4; o > 0; o >>= 1) v += __shfl_down_sync(0xffffffffu, v, o);
    }
    return v;  // valid in thread 0
}

// ---- fused GEMM: C = sigmoid(A @ B^T + bias) ----
// A: M x K row-major, B: Nc x K row-major (both K-contiguous -> NT GEMM), C: M x Nc
#define BM 128
#define BN 128
#define BK 16

__global__ void __launch_bounds__(256)
gemm_nt_bias_sigmoid(const float* __restrict__ A, const float* __restrict__ B,
                     const float* __restrict__ bias, float* __restrict__ C,
                     int M, int Nc, int K)
{
    __shared__ float As[BK][BM + 4];
    __shared__ float Bs[BK][BN + 4];

    const int tid = threadIdx.x;      // 256 threads
    const int tx  = tid & 15;         // 0..15 -> n
    const int ty  = tid >> 4;         // 0..15 -> m
    const int bm0 = blockIdx.y * BM;
    const int bn0 = blockIdx.x * BN;

    float acc[8][8];
#pragma unroll
    for (int i = 0; i < 8; i++)
#pragma unroll
        for (int j = 0; j < 8; j++) acc[i][j] = 0.f;

    const int row0 = tid >> 2;          // 0..63
    const int kq   = (tid & 3) << 2;    // 0,4,8,12

    for (int kt = 0; kt < K; kt += BK) {
#pragma unroll
        for (int i = 0; i < 2; i++) {
            int row = row0 + i * 64;
            float4 a = *(const float4*)(A + (size_t)(bm0 + row) * K + kt + kq);
            float4 b = *(const float4*)(B + (size_t)(bn0 + row) * K + kt + kq);
            As[kq + 0][row] = a.x; As[kq + 1][row] = a.y;
            As[kq + 2][row] = a.z; As[kq + 3][row] = a.w;
            Bs[kq + 0][row] = b.x; Bs[kq + 1][row] = b.y;
            Bs[kq + 2][row] = b.z; Bs[kq + 3][row] = b.w;
        }
        __syncthreads();
#pragma unroll
        for (int k = 0; k < BK; k++) {
            float ar[8], br[8];
            *(float4*)&ar[0] = *(const float4*)&As[k][ty * 8];
            *(float4*)&ar[4] = *(const float4*)&As[k][ty * 8 + 4];
            *(float4*)&br[0] = *(const float4*)&Bs[k][tx * 8];
            *(float4*)&br[4] = *(const float4*)&Bs[k][tx * 8 + 4];
#pragma unroll
            for (int m = 0; m < 8; m++)
#pragma unroll
                for (int n = 0; n < 8; n++)
                    acc[m][n] = fmaf(ar[m], br[n], acc[m][n]);
        }
        __syncthreads();
    }

    float bs[8];
#pragma unroll
    for (int n = 0; n < 8; n++) bs[n] = bias[bn0 + tx * 8 + n];

#pragma unroll
    for (int m = 0; m < 8; m++) {
        float o[8];
#pragma unroll
        for (int n = 0; n < 8; n++) {
            float v = acc[m][n] + bs[n];
            o[n] = 1.f / (1.f + __expf(-v));
        }
        float* cp = C + (size_t)(bm0 + ty * 8 + m) * Nc + bn0 + tx * 8;
        *(float4*)cp       = make_float4(o[0], o[1], o[2], o[3]);
        *(float4*)(cp + 4) = make_float4(o[4], o[5], o[6], o[7]);
    }
}

// ---- per-node residual: d2[n] = || A[n,:] - H2[n,:] || ----
__global__ void node_residual_kernel(const float* __restrict__ A) {
    int n = blockIdx.x;
    const float4* a = (const float4*)(A    + (size_t)n * NN);
    const float4* h = (const float4*)(g_H2 + (size_t)n * NN);
    float s = 0.f;
    for (int c = threadIdx.x; c < NN / 4; c += blockDim.x) {
        float4 x = a[c], y = h[c];
        float d0 = x.x - y.x, d1 = x.y - y.y, d2v = x.z - y.z, d3 = x.w - y.w;
        s += d0 * d0 + d1 * d1 + d2v * d2v + d3 * d3;
    }
    s = block_reduce(s);
    if (threadIdx.x == 0) g_d2[n] = sqrtf(s);
}

// ---- per-edge losses ----
__global__ void edge_loss_kernel(const int* __restrict__ edges,
                                 const int* __restrict__ labels) {
    int e  = blockIdx.x;
    int ni = edges[2 * e + 0];
    int nj = edges[2 * e + 1];
    int lab = labels[e];

    if (lab != 0) {  // uniform across block
        const float4* hi1 = (const float4*)(g_H1 + (size_t)ni * HD);
        const float4* hj1 = (const float4*)(g_H1 + (size_t)nj * HD);
        float s1 = 0.f;
        for (int c = threadIdx.x; c < HD / 4; c += blockDim.x) {
            float4 x = hi1[c], y = hj1[c];
            float d0 = x.x - y.x, d1 = x.y - y.y, d2v = x.z - y.z, d3 = x.w - y.w;
            s1 += d0 * d0 + d1 * d1 + d2v * d2v + d3 * d3;
        }
        const float4* hi2 = (const float4*)(g_H2 + (size_t)ni * NN);
        const float4* hj2 = (const float4*)(g_H2 + (size_t)nj * NN);
        float s2 = 0.f;
        for (int c = threadIdx.x; c < NN / 4; c += blockDim.x) {
            float4 x = hi2[c], y = hj2[c];
            float d0 = x.x - y.x, d1 = x.y - y.y, d2v = x.z - y.z, d3 = x.w - y.w;
            s2 += d0 * d0 + d1 * d1 + d2v * d2v + d3 * d3;
        }
        s1 = block_reduce(s1);
        s2 = block_reduce(s2);
        if (threadIdx.x == 0) atomicAdd(&g_acc[0], sqrtf(s1) + sqrtf(s2));
    }
    if (threadIdx.x == 0) {
        float factor = (lab != 0) ? 10.f : 1.f;  // PENALTY = 10
        atomicAdd(&g_acc[1], factor * (g_d2[ni] + g_d2[nj]));
    }
}

// ---- regularizer: sum of row norms of W1, W2 plus ||b1||, ||b2|| ----
__global__ void reg_norm_kernel(const float* __restrict__ W1, const float* __restrict__ b1,
                                const float* __restrict__ W2, const float* __restrict__ b2) {
    int b = blockIdx.x;
    const float* p; int len;
    if (b < HD)            { p = W1 + (size_t)b * NN;        len = NN; }
    else if (b < HD + NN)  { p = W2 + (size_t)(b - HD) * HD; len = HD; }
    else if (b == HD + NN) { p = b1;                         len = HD; }
    else                   { p = b2;                         len = NN; }
    float s = 0.f;
    for (int c = threadIdx.x; c < len; c += blockDim.x) { float v = p[c]; s += v * v; }
    s = block_reduce(s);
    if (threadIdx.x == 0) atomicAdd(&g_acc[2], sqrtf(s));
}

__global__ void finalize_kernel(float* out) {
    out[0] = g_acc[0] + g_acc[1] + g_acc[2] * (float)EE;
}

extern "C" void kernel_launch(void* const* d_in, const int* in_sizes, int n_in,
                              void* d_out, int out_size) {
    const float* A     = (const float*)d_in[0];
    const float* W1    = (const float*)d_in[1];
    const float* b1    = (const float*)d_in[2];
    const float* W2    = (const float*)d_in[3];
    const float* b2    = (const float*)d_in[4];
    const int*   edges = (const int*)d_in[5];
    const int*   labels= (const int*)d_in[6];
    float* out = (float*)d_out;

    float *H1p = nullptr, *H2p = nullptr;
    cudaGetSymbolAddress((void**)&H1p, g_H1);
    cudaGetSymbolAddress((void**)&H2p, g_H2);

    zero_acc_kernel<<<1, 1>>>();

    // H1 = sigmoid(A @ W1^T + b1): M=8192, Nc=1024, K=8192
    gemm_nt_bias_sigmoid<<<dim3(HD / BN, NN / BM), 256>>>(A, W1, b1, H1p, NN, HD, NN);
    // H2 = sigmoid(H1 @ W2^T + b2): M=8192, Nc=8192, K=1024
    gemm_nt_bias_sigmoid<<<dim3(NN / BN, NN / BM), 256>>>(H1p, W2, b2, H2p, NN, NN, HD);

    node_residual_kernel<<<NN, 256>>>(A);
    edge_loss_kernel<<<EE, 256>>>(edges, labels);
    reg_norm_kernel<<<HD + NN + 2, 256>>>(W1, b1, W2, b2);
    finalize_kernel<<<1, 1>>>(out);
}

// round 3
// speedup vs baseline: 5.8507x; 5.8507x over previous
#include <cuda_runtime.h>
#include <cuda_bf16.h>
#include <cstdint>
#include <math.h>

#define NN 8192
#define HD 1024
#define EE 8192

// ---------------- scratch (device globals; allocation-free) ----------------
__device__ __nv_bfloat16 g_Abf[(size_t)NN * NN];   // 128 MB
__device__ __nv_bfloat16 g_W1bf[(size_t)HD * NN];  // 16 MB
__device__ __nv_bfloat16 g_W2bf[(size_t)NN * HD];  // 16 MB
__device__ __nv_bfloat16 g_H1bf[(size_t)NN * HD];  // 16 MB
__device__ __nv_bfloat16 g_H2bf[(size_t)NN * NN];  // 128 MB
__device__ float g_d2[NN];
__device__ float g_acc[3];

// ---------------- PTX helpers ----------------
__device__ __forceinline__ uint32_t smem_u32(const void* p) {
    uint32_t a;
    asm("{ .reg .u64 t; cvta.to.shared.u64 t, %1; cvt.u32.u64 %0, t; }" : "=r"(a) : "l"(p));
    return a;
}

#define CP_ASYNC16(dst, src) \
    asm volatile("cp.async.cg.shared.global [%0], [%1], 16;" :: "r"(dst), "l"(src) : "memory")
#define CP_COMMIT() asm volatile("cp.async.commit_group;" ::: "memory")
template <int N>
__device__ __forceinline__ void cp_wait() {
    asm volatile("cp.async.wait_group %0;" :: "n"(N) : "memory");
}

__device__ __forceinline__ void ldsm4(uint32_t* r, uint32_t addr) {
    asm volatile("ldmatrix.sync.aligned.m8n8.x4.shared.b16 {%0,%1,%2,%3}, [%4];"
                 : "=r"(r[0]), "=r"(r[1]), "=r"(r[2]), "=r"(r[3]) : "r"(addr));
}

__device__ __forceinline__ void mma_bf16(float* c, const uint32_t* a,
                                         uint32_t b0, uint32_t b1) {
    asm volatile(
        "mma.sync.aligned.m16n8k16.row.col.f32.bf16.bf16.f32 "
        "{%0,%1,%2,%3}, {%4,%5,%6,%7}, {%8,%9}, {%0,%1,%2,%3};"
        : "+f"(c[0]), "+f"(c[1]), "+f"(c[2]), "+f"(c[3])
        : "r"(a[0]), "r"(a[1]), "r"(a[2]), "r"(a[3]), "r"(b0), "r"(b1));
}

// ---------------- bf16 HMMA GEMM: H = sigmoid(A @ B^T + bias) ----------------
// A: [M, K] bf16 row-major; B: [Nc, K] bf16 row-major (NT); H: [M, Nc] bf16.
// CTA tile 128x128, BK=64, 3-stage cp.async pipeline, 8 warps (2x4), warp 64x32.
#define STAGE_BYTES 32768          // A 16K + B 16K
#define SMEM_BYTES (3 * STAGE_BYTES)

// one stage: A tile 128x64 bf16 + B tile 128x64 bf16, SW128 swizzled
__device__ __forceinline__ void load_stage(
    const __nv_bfloat16* __restrict__ Abf, const __nv_bfloat16* __restrict__ Bbf,
    int K, int bm0, int bn0, int kt, uint32_t stageBase, int tid)
{
#pragma unroll
    for (int r = 0; r < 4; r++) {
        int idx = tid + r * 256;           // 0..1023
        int row = idx >> 3, ck = idx & 7;  // 128 rows x 8 chunks of 16B
        uint32_t off = (uint32_t)(row * 128 + ck * 16);
        uint32_t sw = off ^ ((off >> 3) & 0x70);
        const void* srcA = (const char*)(Abf + (size_t)(bm0 + row) * K + kt) + ck * 16;
        CP_ASYNC16(stageBase + sw, srcA);
        const void* srcB = (const char*)(Bbf + (size_t)(bn0 + row) * K + kt) + ck * 16;
        CP_ASYNC16(stageBase + 16384 + sw, srcB);
    }
    CP_COMMIT();
}

__global__ void __launch_bounds__(256)
gemm_hmma_bias_sigmoid(const __nv_bfloat16* __restrict__ Abf,
                       const __nv_bfloat16* __restrict__ Bbf,
                       const float* __restrict__ bias,
                       __nv_bfloat16* __restrict__ Hout,
                       int K, int Nc)
{
    extern __shared__ __align__(1024) char smem[];
    const uint32_t sb0 = smem_u32(smem);
    const int tid = threadIdx.x;
    const int wid = tid >> 5, lid = tid & 31;
    const int warp_m = wid >> 2;     // 0..1 -> 64 rows
    const int warp_n = wid & 3;      // 0..3 -> 32 cols
    const int bm0 = blockIdx.y * 128;
    const int bn0 = blockIdx.x * 128;

    // per-lane ldmatrix addressing constants
    const int q  = lid >> 3;         // matrix index 0..3
    const int r8 = lid & 7;
    const int arowb = warp_m * 64 + (q & 1) * 8 + r8;   // + mt*16
    const int browb = warp_n * 32 + (q & 1) * 8 + r8;   // + bt*16
    const uint32_t kq   = (uint32_t)((q >> 1) * 16);
    const uint32_t axor = (uint32_t)((arowb & 7) << 4);
    const uint32_t bxor = (uint32_t)((browb & 7) << 4);

    float acc[4][4][4];
#pragma unroll
    for (int i = 0; i < 4; i++)
#pragma unroll
        for (int j = 0; j < 4; j++)
#pragma unroll
            for (int k = 0; k < 4; k++) acc[i][j][k] = 0.f;

    const int T = K >> 6;            // K/64 chunks

    load_stage(Abf, Bbf, K, bm0, bn0, 0, sb0, tid);
    load_stage(Abf, Bbf, K, bm0, bn0, 64, sb0 + STAGE_BYTES, tid);

    for (int i = 0; i < T; i++) {
        if (i < T - 1) cp_wait<1>(); else cp_wait<0>();
        __syncthreads();
        if (i + 2 < T) {
            int pb = (i + 2) % 3;
            load_stage(Abf, Bbf, K, bm0, bn0, (i + 2) * 64,
                       sb0 + (uint32_t)pb * STAGE_BYTES, tid);
        }
        const uint32_t Ab = sb0 + (uint32_t)(i % 3) * STAGE_BYTES;
        const uint32_t Bb = Ab + 16384;

#pragma unroll
        for (int s = 0; s < 4; s++) {
            const uint32_t koff = (uint32_t)(s * 32) | kq;
            uint32_t a[4][4], bfr[2][4];
#pragma unroll
            for (int mt = 0; mt < 4; mt++)
                ldsm4(a[mt], Ab + (uint32_t)(arowb + mt * 16) * 128 + (koff ^ axor));
#pragma unroll
            for (int bt = 0; bt < 2; bt++)
                ldsm4(bfr[bt], Bb + (uint32_t)(browb + bt * 16) * 128 + (koff ^ bxor));
#pragma unroll
            for (int mt = 0; mt < 4; mt++)
#pragma unroll
                for (int nt = 0; nt < 4; nt++)
                    mma_bf16(acc[mt][nt], a[mt], bfr[nt >> 1][nt & 1], bfr[nt >> 1][(nt & 1) + 2]);
        }
        __syncthreads();
    }

    // epilogue: bias + sigmoid + bf16 store (acc layout: c0,c1 @ row l/4; c2,c3 @ +8)
    const int rr = lid >> 2;              // 0..7
    const int cc = (lid & 3) * 2;
#pragma unroll
    for (int nt = 0; nt < 4; nt++) {
        const int col = bn0 + warp_n * 32 + nt * 8 + cc;
        const float bb0 = bias[col], bb1 = bias[col + 1];
#pragma unroll
        for (int mt = 0; mt < 4; mt++) {
            const int row0 = bm0 + warp_m * 64 + mt * 16 + rr;
            float v0 = acc[mt][nt][0] + bb0, v1 = acc[mt][nt][1] + bb1;
            float v2 = acc[mt][nt][2] + bb0, v3 = acc[mt][nt][3] + bb1;
            float s0 = 1.f / (1.f + __expf(-v0));
            float s1 = 1.f / (1.f + __expf(-v1));
            float s2 = 1.f / (1.f + __expf(-v2));
            float s3 = 1.f / (1.f + __expf(-v3));
            __nv_bfloat162 h01 = __floats2bfloat162_rn(s0, s1);
            __nv_bfloat162 h23 = __floats2bfloat162_rn(s2, s3);
            *(uint32_t*)(Hout + (size_t)row0 * Nc + col)       = *(uint32_t*)&h01;
            *(uint32_t*)(Hout + (size_t)(row0 + 8) * Nc + col) = *(uint32_t*)&h23;
        }
    }
}

// ---------------- fp32 -> bf16 conversion ----------------
__global__ void f32_to_bf16(const float4* __restrict__ in, uint2* __restrict__ out, int n4) {
    int i = blockIdx.x * blockDim.x + threadIdx.x;
    if (i < n4) {
        float4 v = in[i];
        __nv_bfloat162 a = __floats2bfloat162_rn(v.x, v.y);
        __nv_bfloat162 b = __floats2bfloat162_rn(v.z, v.w);
        out[i] = make_uint2(*(uint32_t*)&a, *(uint32_t*)&b);
    }
}

// ---------------- reductions ----------------
__device__ __forceinline__ float block_reduce(float v) {
    __shared__ float sh[8];
    __syncthreads();
    int lane = threadIdx.x & 31;
    int w    = threadIdx.x >> 5;
#pragma unroll
    for (int o = 16; o > 0; o >>= 1) v += __shfl_down_sync(0xffffffffu, v, o);
    if (lane == 0) sh[w] = v;
    __syncthreads();
    if (w == 0) {
        v = (lane < 8) ? sh[lane] : 0.f;
#pragma unroll
        for (int o = 4; o > 0; o >>= 1) v += __shfl_down_sync(0xffffffffu, v, o);
    }
    return v;
}

__device__ __forceinline__ float d2_bf8(uint4 x, uint4 y) {
    float s = 0.f;
    const uint32_t* xp = (const uint32_t*)&x;
    const uint32_t* yp = (const uint32_t*)&y;
#pragma unroll
    for (int qq = 0; qq < 4; qq++) {
        float2 a = __bfloat1622float2(*(const __nv_bfloat162*)&xp[qq]);
        float2 b = __bfloat1622float2(*(const __nv_bfloat162*)&yp[qq]);
        float d0 = a.x - b.x, d1 = a.y - b.y;
        s += d0 * d0 + d1 * d1;
    }
    return s;
}

__global__ void zero_acc_kernel() { g_acc[0] = 0.f; g_acc[1] = 0.f; g_acc[2] = 0.f; }

// d2[n] = || A[n,:] - H2[n,:] ||
__global__ void node_residual_kernel(const float* __restrict__ A) {
    int n = blockIdx.x;
    const float4* a = (const float4*)(A + (size_t)n * NN);
    const uint2* h  = (const uint2*)(g_H2bf + (size_t)n * NN);
    float s = 0.f;
    for (int c = threadIdx.x; c < NN / 4; c += blockDim.x) {
        float4 x = a[c];
        uint2 hh = h[c];
        float2 h0 = __bfloat1622float2(*(const __nv_bfloat162*)&hh.x);
        float2 h1 = __bfloat1622float2(*(const __nv_bfloat162*)&hh.y);
        float d0 = x.x - h0.x, d1 = x.y - h0.y, d2v = x.z - h1.x, d3 = x.w - h1.y;
        s += d0 * d0 + d1 * d1 + d2v * d2v + d3 * d3;
    }
    s = block_reduce(s);
    if (threadIdx.x == 0) g_d2[n] = sqrtf(s);
}

__global__ void edge_loss_kernel(const int* __restrict__ edges,
                                 const int* __restrict__ labels) {
    int e  = blockIdx.x;
    int ni = edges[2 * e + 0];
    int nj = edges[2 * e + 1];
    int lab = labels[e];

    if (lab != 0) {
        const uint4* hi1 = (const uint4*)(g_H1bf + (size_t)ni * HD);
        const uint4* hj1 = (const uint4*)(g_H1bf + (size_t)nj * HD);
        float s1 = 0.f;
        for (int c = threadIdx.x; c < HD / 8; c += blockDim.x)
            s1 += d2_bf8(hi1[c], hj1[c]);
        const uint4* hi2 = (const uint4*)(g_H2bf + (size_t)ni * NN);
        const uint4* hj2 = (const uint4*)(g_H2bf + (size_t)nj * NN);
        float s2 = 0.f;
        for (int c = threadIdx.x; c < NN / 8; c += blockDim.x)
            s2 += d2_bf8(hi2[c], hj2[c]);
        s1 = block_reduce(s1);
        s2 = block_reduce(s2);
        if (threadIdx.x == 0) atomicAdd(&g_acc[0], sqrtf(s1) + sqrtf(s2));
    }
    if (threadIdx.x == 0) {
        float factor = (lab != 0) ? 10.f : 1.f;
        atomicAdd(&g_acc[1], factor * (g_d2[ni] + g_d2[nj]));
    }
}

// sum of row norms of W1, W2 plus ||b1||, ||b2|| (exact, fp32 inputs)
__global__ void reg_norm_kernel(const float* __restrict__ W1, const float* __restrict__ b1,
                                const float* __restrict__ W2, const float* __restrict__ b2) {
    int b = blockIdx.x;
    const float* p; int len;
    if (b < HD)            { p = W1 + (size_t)b * NN;        len = NN; }
    else if (b < HD + NN)  { p = W2 + (size_t)(b - HD) * HD; len = HD; }
    else if (b == HD + NN) { p = b1;                         len = HD; }
    else                   { p = b2;                         len = NN; }
    float s = 0.f;
    for (int c = threadIdx.x; c < len; c += blockDim.x) { float v = p[c]; s += v * v; }
    s = block_reduce(s);
    if (threadIdx.x == 0) atomicAdd(&g_acc[2], sqrtf(s));
}

__global__ void finalize_kernel(float* out) {
    out[0] = g_acc[0] + g_acc[1] + g_acc[2] * (float)EE;
}

// ---------------- launch ----------------
extern "C" void kernel_launch(void* const* d_in, const int* in_sizes, int n_in,
                              void* d_out, int out_size) {
    const float* A      = (const float*)d_in[0];
    const float* W1     = (const float*)d_in[1];
    const float* b1     = (const float*)d_in[2];
    const float* W2     = (const float*)d_in[3];
    const float* b2     = (const float*)d_in[4];
    const int*   edges  = (const int*)d_in[5];
    const int*   labels = (const int*)d_in[6];
    float* out = (float*)d_out;

    __nv_bfloat16 *Abf, *W1bf, *W2bf, *H1bf, *H2bf;
    cudaGetSymbolAddress((void**)&Abf,  g_Abf);
    cudaGetSymbolAddress((void**)&W1bf, g_W1bf);
    cudaGetSymbolAddress((void**)&W2bf, g_W2bf);
    cudaGetSymbolAddress((void**)&H1bf, g_H1bf);
    cudaGetSymbolAddress((void**)&H2bf, g_H2bf);

    cudaFuncSetAttribute(gemm_hmma_bias_sigmoid,
                         cudaFuncAttributeMaxDynamicSharedMemorySize, SMEM_BYTES);

    zero_acc_kernel<<<1, 1>>>();

    // fp32 -> bf16 conversions
    f32_to_bf16<<<(NN * (NN / 4) + 255) / 256, 256>>>((const float4*)A,  (uint2*)Abf,  NN * NN / 4);
    f32_to_bf16<<<(HD * (NN / 4) + 255) / 256, 256>>>((const float4*)W1, (uint2*)W1bf, HD * NN / 4);
    f32_to_bf16<<<(NN * (HD / 4) + 255) / 256, 256>>>((const float4*)W2, (uint2*)W2bf, NN * HD / 4);

    // H1 = sigmoid(A @ W1^T + b1): M=8192, Nc=1024, K=8192
    gemm_hmma_bias_sigmoid<<<dim3(HD / 128, NN / 128), 256, SMEM_BYTES>>>(
        Abf, W1bf, b1, H1bf, NN, HD);
    // H2 = sigmoid(H1 @ W2^T + b2): M=8192, Nc=8192, K=1024
    gemm_hmma_bias_sigmoid<<<dim3(NN / 128, NN / 128), 256, SMEM_BYTES>>>(
        H1bf, W2bf, b2, H2bf, HD, NN);

    node_residual_kernel<<<NN, 256>>>(A);
    edge_loss_kernel<<<EE, 256>>>(edges, labels);
    reg_norm_kernel<<<HD + NN + 2, 256>>>(W1, b1, W2, b2);
    finalize_kernel<<<1, 1>>>(out);
}